// round 13
// baseline (speedup 1.0000x reference)
#include <cuda_runtime.h>
#include <cuda_fp16.h>
#include <cstdint>

#define Hh 512
#define Ww 512
#define CIN 64
#define KOC 128
#define HWSZ (Hh*Ww)
#define NT 9

#define SWZ(o) ((o) ^ ((((uint32_t)(o))>>3)&0x70))

// ---- dynamic smem layout (101 KB -> 2 CTAs/SM) ----
#define SCL    0
#define SHF    512
#define ABASE  1024
#define AROWS  136
#define ABUFSZ (AROWS*128)                   // 17408
#define ABUF(i) (ABASE + (i)*ABUFSZ)         // 4 buffers: srow r0-1 .. r0+2
#define WBASE  (ABASE + 4*ABUFSZ)            // 70656
#define WBUF(b) (WBASE + (b)*16384)          // double-buffered W, fp16
#define SMEM_TOTAL (WBASE + 2*16384)         // 103424

__device__ __align__(16) unsigned char Wb[NT*16384];   // pre-swizzled fp16 W tiles

static __device__ __forceinline__ uint32_t s2u(const void* p){
    uint32_t a;
    asm("{ .reg .u64 t; cvta.to.shared.u64 t, %1; cvt.u32.u64 %0, t; }":"=r"(a):"l"(p));
    return a;
}
static __device__ __forceinline__ void ldsm4(uint32_t addr,
        uint32_t &r0, uint32_t &r1, uint32_t &r2, uint32_t &r3){
    asm volatile("ldmatrix.sync.aligned.m8n8.x4.shared.b16 {%0,%1,%2,%3}, [%4];"
        : "=r"(r0),"=r"(r1),"=r"(r2),"=r"(r3) : "r"(addr));
}
static __device__ __forceinline__ void hmma(float* c,
        uint32_t a0,uint32_t a1,uint32_t a2,uint32_t a3,
        uint32_t b0,uint32_t b1){
    asm volatile("mma.sync.aligned.m16n8k16.row.col.f32.f16.f16.f32 "
        "{%0,%1,%2,%3}, {%4,%5,%6,%7}, {%8,%9}, {%0,%1,%2,%3};"
        : "+f"(c[0]),"+f"(c[1]),"+f"(c[2]),"+f"(c[3])
        : "r"(a0),"r"(a1),"r"(a2),"r"(a3),"r"(b0),"r"(b1));
}
static __device__ __forceinline__ void cpasync16(uint32_t daddr, const void* g){
    asm volatile("cp.async.cg.shared.global [%0], [%1], 16;" :: "r"(daddr), "l"(g) : "memory");
}
static __device__ __forceinline__ void cpcommit(){
    asm volatile("cp.async.commit_group;" ::: "memory");
}
template<int N> static __device__ __forceinline__ void cpwait(){
    asm volatile("cp.async.wait_group %0;" :: "n"(N) : "memory");
}

// ---------- prep: W -> fp16, pre-swizzled K-major SW128 tiles (rows = oc) ----------
__global__ void prep_w(const float* __restrict__ Wt){
    int idx = blockIdx.x * blockDim.x + threadIdx.x;   // 9*128*64
    if (idx >= NT*KOC*CIN) return;
    int t   = idx >> 13;
    int rem = idx & 8191;
    int n   = rem >> 6;
    int kk  = rem & 63;
    float v = Wt[(n*CIN + kk)*9 + t];
    uint32_t off = SWZ((uint32_t)(n*128 + kk*2));
    *(__half*)(Wb + t*16384 + off) = __float2half_rn(v);
}

// stage one reflected image row (64 ch x 130 px, fp16) into A buffer `bi`
static __device__ __forceinline__ void stage_row(
        char* sm, const float* __restrict__ x, int srow, int col0, int bi,
        int w, int lane){
    srow = (srow < 0) ? -srow : ((srow > Hh-1) ? (2*Hh-2 - srow) : srow);
    const float* xrow = x + (size_t)srow * Ww;
    #pragma unroll
    for (int ii = 0; ii < 5; ++ii) {
        const int ipix = lane + 32*ii;
        if (ipix < 130) {
            int cc = col0 - 1 + ipix;
            cc = (cc < 0) ? -cc : ((cc > Ww-1) ? (2*Ww-2 - cc) : cc);
            float v[8];
            #pragma unroll
            for (int j = 0; j < 8; ++j)
                v[j] = __ldg(xrow + (size_t)(w*8 + j) * HWSZ + cc);
            uint32_t hw4[4];
            #pragma unroll
            for (int q = 0; q < 4; ++q) {
                __half2 hp = __floats2half2_rn(v[2*q], v[2*q+1]);
                hw4[q] = *(uint32_t*)&hp;
            }
            const uint32_t off = SWZ((uint32_t)(ipix*128 + w*16));
            *(uint4*)(sm + ABUF(bi) + off) = make_uint4(hw4[0],hw4[1],hw4[2],hw4[3]);
        }
    }
}

// BN + LeakyReLU + mask epilogue for one output row
static __device__ __forceinline__ void epilogue(
        float (&acc)[2][8][4], const float* s_scale, const float* s_shift,
        const int* __restrict__ mask, float* __restrict__ out,
        int row, int col0, int wpix, int woc, int lane){
    const int pixc = (lane & 3) << 1;
    const int ocr  = lane >> 2;
    #pragma unroll
    for (int msub = 0; msub < 2; ++msub) {
        #pragma unroll
        for (int n = 0; n < 8; ++n) {
            const int pix = row*Ww + col0 + wpix*64 + n*8 + pixc;
            #pragma unroll
            for (int h = 0; h < 2; ++h) {
                const int oc = woc*32 + msub*16 + ocr + h*8;
                const float sc = s_scale[oc];
                const float sh = s_shift[oc];
                const int base = oc*HWSZ + pix;
                const int2 m2 = *(const int2*)(mask + base);
                float y0 = fmaf(acc[msub][n][h*2+0], sc, sh);
                float y1 = fmaf(acc[msub][n][h*2+1], sc, sh);
                y0 = (y0 >= 0.f) ? y0 : 0.01f * y0;
                y1 = (y1 >= 0.f) ? y1 : 0.01f * y1;
                float2 rv;
                rv.x = y0 * (float)m2.x;
                rv.y = y1 * (float)m2.y;
                *(float2*)(out + base) = rv;
            }
        }
    }
}

// ---------- main fused kernel: fp16 1-pass, M=oc(128) x N=pix(128), row-pair CTAs ----------
__global__ void __launch_bounds__(256,2)
conv_mma_f16(const float* __restrict__ x,
             const float* __restrict__ gamma, const float* __restrict__ beta,
             const float* __restrict__ mean,  const float* __restrict__ var,
             const int*   __restrict__ mask,  float* __restrict__ out)
{
    extern __shared__ __align__(1024) char sm[];
    const uint32_t smb = s2u(sm);

    const int tid  = threadIdx.x;
    const int w    = tid >> 5;
    const int lane = tid & 31;
    const int wpix = w >> 2;           // 0..1 : pixel offset wpix*64 (N dim)
    const int woc  = w & 3;            // 0..3 : oc offset woc*32   (M dim)

    float* s_scale = (float*)(sm + SCL);
    float* s_shift = (float*)(sm + SHF);
    if (tid < KOC) {
        float sc = gamma[tid] * rsqrtf(var[tid] + 1e-5f);
        s_scale[tid] = sc;
        s_shift[tid] = beta[tid] - mean[tid] * sc;
    }

    const int bid  = blockIdx.x;        // 1024
    const int r0   = (bid >> 2) * 2;    // first output row of the pair
    const int col0 = (bid & 3) * 128;   // 128-col pixel tile

    float acc[2][8][4];
    #pragma unroll
    for (int m = 0; m < 2; ++m)
        #pragma unroll
        for (int n = 0; n < 8; ++n)
            #pragma unroll
            for (int e = 0; e < 4; ++e) acc[m][n][e] = 0.f;

    // ldmatrix lane geometry
    const int jj = lane >> 3, rr = lane & 7;
    const int a_row_l = ((jj & 1) << 3) + rr;
    const int a_col_l = (jj >> 1) << 4;
    const int b_row_l = ((jj >> 1) << 3) + rr;
    const int b_col_l = (jj & 1) << 4;

    // ---- prologue: async-prefetch W tap 0; stage srows r0-1, r0, r0+1 ----
    {
        const uint32_t d = smb + WBUF(0);
        #pragma unroll
        for (int p = 0; p < 4; ++p)
            cpasync16(d + (tid + p*256)*16, (const char*)Wb + (tid + p*256)*16);
        cpcommit();
    }
    #pragma unroll
    for (int i = 0; i < 3; ++i)
        stage_row(sm, x, r0 - 1 + i, col0, i, w, lane);

    // ---- flattened loop: 2 output rows x 9 taps ----
    for (int it = 0; it < 2*NT; ++it) {
        const int ch     = (it >= NT) ? it - NT : it;
        const int rowsel = (it >= NT) ? 1 : 0;

        __syncthreads();     // all reads of WBUF((it+1)&1) from it-1 complete

        if (it + 1 < 2*NT) { // prefetch W for next iteration
            const int chn = (it + 1 >= NT) ? it + 1 - NT : it + 1;
            const uint32_t d = smb + WBUF((it+1) & 1);
            const char* sh = (const char*)Wb + chn*16384;
            #pragma unroll
            for (int p = 0; p < 4; ++p)
                cpasync16(d + (tid + p*256)*16, sh + (tid + p*256)*16);
            cpcommit();
            cpwait<1>();     // W(it) has landed
        } else {
            cpwait<0>();
        }
        __syncthreads();     // W(it) (+ staged A) visible to all warps

        const int bi     = ch/3 + rowsel;    // A buffer for this tap
        const int rowoff = ch - (ch/3)*3;    // dx+1
        const uint32_t wb = smb + WBUF(it & 1);
        const uint32_t ab = smb + ABUF(bi);

        #pragma unroll
        for (int ks = 0; ks < 4; ++ks) {
            const int kbyte = ks*32;
            uint32_t bp[16];                 // pixel B-frags: 64 pix = 4 ldsm4
            #pragma unroll
            for (int np = 0; np < 4; ++np) {
                const int prow = wpix*64 + np*16 + b_row_l + rowoff;
                const uint32_t poff = SWZ((uint32_t)(prow*128 + kbyte + b_col_l));
                ldsm4(ab + poff, bp[np*4+0], bp[np*4+1], bp[np*4+2], bp[np*4+3]);
            }
            #pragma unroll
            for (int msub = 0; msub < 2; ++msub) {
                const int wrow = woc*32 + msub*16 + a_row_l;
                const uint32_t woff = SWZ((uint32_t)(wrow*128 + kbyte + a_col_l));
                uint32_t ah[4];
                ldsm4(wb + woff, ah[0], ah[1], ah[2], ah[3]);
                #pragma unroll
                for (int n = 0; n < 8; ++n)
                    hmma(acc[msub][n], ah[0],ah[1],ah[2],ah[3],
                         bp[n*2], bp[n*2+1]);
            }
        }

        if (it == 0) {
            // stage srow r0+2 into buffer 3 (first needed at it=12); hides under MMA
            stage_row(sm, x, r0 + 2, col0, 3, w, lane);
        }
        if (it == NT-1) {
            // mid-epilogue: output row r0, then reset acc for row r0+1
            epilogue(acc, s_scale, s_shift, mask, out, r0, col0, wpix, woc, lane);
            #pragma unroll
            for (int m = 0; m < 2; ++m)
                #pragma unroll
                for (int n = 0; n < 8; ++n)
                    #pragma unroll
                    for (int e = 0; e < 4; ++e) acc[m][n][e] = 0.f;
        }
    }

    // ---- final epilogue: output row r0+1 ----
    epilogue(acc, s_scale, s_shift, mask, out, r0 + 1, col0, wpix, woc, lane);
}

extern "C" void kernel_launch(void* const* d_in, const int* in_sizes, int n_in,
                              void* d_out, int out_size)
{
    const float* x     = (const float*)d_in[0];
    const float* Wt    = (const float*)d_in[1];
    const float* gamma = (const float*)d_in[2];
    const float* beta  = (const float*)d_in[3];
    const float* mean  = (const float*)d_in[4];
    const float* var   = (const float*)d_in[5];
    const int*   mask  = (const int*)d_in[6];
    float*       out   = (float*)d_out;

    cudaFuncSetAttribute(conv_mma_f16, cudaFuncAttributeMaxDynamicSharedMemorySize, SMEM_TOTAL);

    prep_w<<<(NT*KOC*CIN + 255)/256, 256>>>(Wt);
    conv_mma_f16<<<1024, 256, SMEM_TOTAL>>>(x, gamma, beta, mean, var, mask, out);
}